// round 14
// baseline (speedup 1.0000x reference)
#include <cuda_runtime.h>
#include <cuda_fp16.h>
#include <math.h>
#include <stdint.h>

#define TT    2048
#define Hdim  768
#define Sq    256
#define NBATCH 8
#define NHEAD 12
#define FFd   3072
#define NEXP  4
#define QKVN  2304
#define NBH   (NBATCH * NHEAD)
#define HH    (Hdim * Hdim)

// ---------------- scratch (device globals) ---------------------------------
__device__ float  g_Xa[TT * Hdim];
__device__ float  g_Xb[TT * Hdim];
__device__ __half g_Hh[TT * Hdim];
__device__ __half g_QKVh[TT * QKVN];
__device__ __half g_midh[TT * FFd];
__device__ float  g_Fo[TT * Hdim];
__device__ float  g_mask[TT];
__device__ int    g_idx[TT];
__device__ int    g_perm[TT];
__device__ int    g_cnt[NEXP];
__device__ int    g_off[NEXP];
__device__ __half g_Wqkvh[2 * 3 * HH];
__device__ __half g_W1h[2 * NEXP * Hdim * FFd];
__device__ __half g_W2h[2 * NEXP * FFd * Hdim];
__device__ float  g_bpk[2 * QKVN];

// ---------------- helpers ---------------------------------------------------
__device__ __forceinline__ float gelu_f(float v) {
    return 0.5f * v * (1.0f + erff(v * 0.70710678118654752f));
}
__device__ __forceinline__ uint32_t smem_u32(const void* p) {
    uint32_t a;
    asm("{ .reg .u64 t; cvta.to.shared.u64 t, %1; cvt.u32.u64 %0, t; }" : "=r"(a) : "l"(p));
    return a;
}
#define SWA(o) ((o) ^ (((o) >> 3) & 0x70))   // 128B rows
#define SWB(o) ((o) ^ (((o) >> 4) & 0x70))   // 256B rows

__device__ __forceinline__ void ldsm4(unsigned r[4], uint32_t addr) {
    asm volatile("ldmatrix.sync.aligned.m8n8.x4.shared.b16 {%0,%1,%2,%3}, [%4];"
                 : "=r"(r[0]), "=r"(r[1]), "=r"(r[2]), "=r"(r[3]) : "r"(addr));
}
__device__ __forceinline__ void ldsm4t(unsigned r[4], uint32_t addr) {
    asm volatile("ldmatrix.sync.aligned.m8n8.x4.trans.shared.b16 {%0,%1,%2,%3}, [%4];"
                 : "=r"(r[0]), "=r"(r[1]), "=r"(r[2]), "=r"(r[3]) : "r"(addr));
}
__device__ __forceinline__ void mma_f16(float c[4], const unsigned a[4],
                                        unsigned b0, unsigned b1) {
    asm volatile(
        "mma.sync.aligned.m16n8k16.row.col.f32.f16.f16.f32 "
        "{%0,%1,%2,%3}, {%4,%5,%6,%7}, {%8,%9}, {%0,%1,%2,%3};\n"
        : "+f"(c[0]), "+f"(c[1]), "+f"(c[2]), "+f"(c[3])
        : "r"(a[0]), "r"(a[1]), "r"(a[2]), "r"(a[3]), "r"(b0), "r"(b1));
}
#define CPASYNC16(dst, src) \
    asm volatile("cp.async.cg.shared.global [%0], [%1], 16;" :: "r"(dst), "l"(src))
#define CPCOMMIT() asm volatile("cp.async.commit_group;" ::: "memory")
#define CPWAIT1() asm volatile("cp.async.wait_group 1;" ::: "memory")
#define CPWAIT0() asm volatile("cp.async.wait_group 0;" ::: "memory")

__device__ __forceinline__ unsigned h2u(__half2 h) { return *(unsigned*)&h; }

// ---------------- weight conversion (32B-store granularity) ------------------
__global__ void f2h_kernel(const float4* __restrict__ src, uint4* __restrict__ dst, int n8) {
    for (int i = blockIdx.x * blockDim.x + threadIdx.x; i < n8;
         i += gridDim.x * blockDim.x) {
        float4 v0 = src[i * 2], v1 = src[i * 2 + 1];
        uint4 u;
        u.x = h2u(__floats2half2_rn(v0.x, v0.y));
        u.y = h2u(__floats2half2_rn(v0.z, v0.w));
        u.z = h2u(__floats2half2_rn(v1.x, v1.y));
        u.w = h2u(__floats2half2_rn(v1.z, v1.w));
        dst[i] = u;
    }
}
__global__ void pack_qkv_h(const float4* __restrict__ Wq, const float4* __restrict__ Wk,
                           const float4* __restrict__ Wv) {
    int y = blockIdx.y, l = y / 3, w = y % 3;
    const float4* src = ((w == 0) ? Wq : (w == 1) ? Wk : Wv) + (size_t)l * (HH / 4);
    uint4* dst = (uint4*)(g_Wqkvh + (size_t)y * HH);
    int i = blockIdx.x * 256 + threadIdx.x;
    if (i < HH / 8) {
        float4 v0 = src[i * 2], v1 = src[i * 2 + 1];
        uint4 u;
        u.x = h2u(__floats2half2_rn(v0.x, v0.y));
        u.y = h2u(__floats2half2_rn(v0.z, v0.w));
        u.z = h2u(__floats2half2_rn(v1.x, v1.y));
        u.w = h2u(__floats2half2_rn(v1.z, v1.w));
        dst[i] = u;
    }
}
__global__ void pack_bias_kernel(const float* __restrict__ bq, const float* __restrict__ bk,
                                 const float* __restrict__ bv) {
    int i = blockIdx.x * 256 + threadIdx.x;
    if (i < 2 * QKVN) {
        int l = i / QKVN, c = i % QKVN;
        int w = c / Hdim, o = c % Hdim;
        const float* s = (w == 0) ? bq : (w == 1) ? bk : bv;
        g_bpk[i] = s[l * Hdim + o];
    }
}

// ---------------- setup: note_pos detect + mask + routing (one block) --------
__global__ void setup_kernel(const void* __restrict__ note_pos_raw,
                             const int* __restrict__ ntp) {
    __shared__ int s_or[256];
    __shared__ int s_is64;
    __shared__ int sc[NEXP], so[NEXP], scur[NEXP];
    const int* w = (const int*)note_pos_raw;
    int tid = threadIdx.x;
    int acc = 0;
    for (int i = tid; i < TT / 2; i += 256) acc |= w[2 * i + 1];
    s_or[tid] = acc; __syncthreads();
    for (int st = 128; st > 0; st >>= 1) {
        if (tid < st) s_or[tid] |= s_or[tid + st];
        __syncthreads();
    }
    if (tid == 0) s_is64 = (s_or[0] == 0);
    if (tid < NEXP) { sc[tid] = 0; scur[tid] = 0; }
    __syncthreads();
    bool is64 = (s_is64 != 0);
    for (int t = tid; t < TT; t += 256) {
        long long v = is64 ? ((const long long*)note_pos_raw)[t] : (long long)w[t];
        g_idx[t] = (int)v;
        g_mask[t] = (v != 0) ? 0.0f : -10000.0f;
        atomicAdd(&sc[ntp[t]], 1);
    }
    __syncthreads();
    if (tid == 0) {
        int o = 0;
        for (int e = 0; e < NEXP; e++) { so[e] = o; o += sc[e]; }
    }
    __syncthreads();
    for (int t = tid; t < TT; t += 256) {
        int e = ntp[t];
        int p = so[e] + atomicAdd(&scur[e], 1);
        g_perm[p] = t;
    }
    __syncthreads();
    if (tid < NEXP) { g_cnt[tid] = sc[tid]; g_off[tid] = so[tid]; }
}

// ---------------- fp16 mma GEMM, 3-stage cp.async pipeline -------------------
// 128 x BNT tile, BK=64, 256 thr.
// MODE 0: QKV fused, fp16 out. MODE 1: FFN1 gather+gelu, fp16 out sorted.
// MODE 2: FFN2, fp32 out scattered via perm.
extern __shared__ char dynsm[];

template <int MODE, int BNT>
__global__ __launch_bounds__(256)
void hgemm(const __half* __restrict__ A, const __half* __restrict__ W,
           const float* __restrict__ bias, void* __restrict__ Cv,
           int K, int Nw, int Cstride) {
    constexpr int NF = BNT / 32;
    constexpr int NG = BNT / 64;
    constexpr int BB = 64 * BNT * 2;
    constexpr int UPT = BNT / 32;
    constexpr int BBASE = 3 * 16384;

    int rowBase = blockIdx.x * 128;
    int myCnt = TT, myOff = 0;
    const __half* Wp;
    const float* bp;
    int colW, outCol;
    if (MODE == 0) {
        int y = blockIdx.y, ws = y / 6, yc = y % 6;
        Wp = W + (size_t)ws * HH;
        colW = yc * 128;
        outCol = y * 128;
        bp = bias + outCol;
    } else {
        int e = blockIdx.z;
        myCnt = g_cnt[e]; myOff = g_off[e];
        if (rowBase >= myCnt) return;
        Wp = W + (size_t)e * K * Nw;
        colW = blockIdx.y * BNT;
        outCol = colW;
        bp = bias + (size_t)e * Nw + colW;
    }

    int tid = threadIdx.x;
    int lane = tid & 31, wid = tid >> 5;
    int warpM = (wid >> 2) * 64;
    int warpN = (wid & 3) * (BNT / 4);
    int gid = lane >> 2, tig = lane & 3;

    uint32_t smA = smem_u32(dynsm);

    int m = tid >> 1;
    int ukb = (tid & 1) * 4;
    bool aValid;
    const __half* ap;
    if (MODE == 0) {
        aValid = true;
        ap = A + (size_t)(rowBase + m) * K;
    } else if (MODE == 1) {
        aValid = (rowBase + m) < myCnt;
        ap = A + (size_t)(aValid ? g_perm[myOff + rowBase + m] : 0) * K;
    } else {
        aValid = (rowBase + m) < myCnt;
        ap = A + (size_t)(myOff + (aValid ? rowBase + m : 0)) * K;
    }
    uint32_t aOff[4];
#pragma unroll
    for (int i = 0; i < 4; i++) aOff[i] = SWA((uint32_t)(m * 128 + (ukb + i) * 16));

    int bk_ = tid >> 2;
    int unb = (tid & 3) * UPT;
    uint32_t bOff[UPT];
#pragma unroll
    for (int i = 0; i < UPT; i++) {
        uint32_t o = (uint32_t)(bk_ * (BNT * 2) + (unb + i) * 16);
        bOff[i] = (BNT == 128) ? SWB(o) : SWA(o);
    }

    int nCh = K >> 6;
    float acc[4][NF][4] = {};

    // prologue: chunks 0 and 1
#pragma unroll
    for (int p = 0; p < 2; p++) {
        uint32_t ab = smA + p * 16384, bb = smA + BBASE + p * BB;
        const __half* as = ap + p * 64 + ukb * 8;
        const __half* bs = Wp + (size_t)(p * 64 + bk_) * Nw + colW + unb * 8;
#pragma unroll
        for (int i = 0; i < 4; i++) CPASYNC16(ab + aOff[i], as + i * 8);
#pragma unroll
        for (int i = 0; i < UPT; i++) CPASYNC16(bb + bOff[i], bs + i * 8);
        CPCOMMIT();
    }

    int rA = lane & 15;
    int cA = (lane >> 4) * 8;

    for (int c = 0; c < nCh; c++) {
        if (c + 2 <= nCh) CPWAIT1(); else CPWAIT0();
        __syncthreads();
        if (c + 2 < nCh) {
            int st = (c + 2) % 3;
            uint32_t ab = smA + st * 16384, bb = smA + BBASE + st * BB;
            const __half* as = ap + (c + 2) * 64 + ukb * 8;
            const __half* bs = Wp + (size_t)((c + 2) * 64 + bk_) * Nw + colW + unb * 8;
#pragma unroll
            for (int i = 0; i < 4; i++) CPASYNC16(ab + aOff[i], as + i * 8);
#pragma unroll
            for (int i = 0; i < UPT; i++) CPASYNC16(bb + bOff[i], bs + i * 8);
            CPCOMMIT();
        }
        int st = c % 3;
        uint32_t aB = smA + st * 16384;
        uint32_t bB = smA + BBASE + st * BB;
#pragma unroll
        for (int ks = 0; ks < 4; ks++) {
            unsigned afr[4][4], bfr[NG][4];
#pragma unroll
            for (int mt = 0; mt < 4; mt++)
                ldsm4(afr[mt], aB + SWA((uint32_t)((warpM + mt * 16 + rA) * 128 +
                                                   (ks * 16 + cA) * 2)));
#pragma unroll
            for (int ng = 0; ng < NG; ng++) {
                uint32_t o = (uint32_t)((ks * 16 + rA) * (BNT * 2) +
                                        (warpN + ng * 16 + cA) * 2);
                ldsm4t(bfr[ng], bB + ((BNT == 128) ? SWB(o) : SWA(o)));
            }
#pragma unroll
            for (int mt = 0; mt < 4; mt++)
#pragma unroll
                for (int nf = 0; nf < NF; nf++)
                    mma_f16(acc[mt][nf], afr[mt],
                            bfr[nf >> 1][(nf & 1) * 2], bfr[nf >> 1][(nf & 1) * 2 + 1]);
        }
        __syncthreads();
    }

#pragma unroll
    for (int mt = 0; mt < 4; mt++) {
#pragma unroll
        for (int hf = 0; hf < 2; hf++) {
            int grow = rowBase + warpM + mt * 16 + gid + hf * 8;
            if (MODE != 0 && grow >= myCnt) continue;
#pragma unroll
            for (int nf = 0; nf < NF; nf++) {
                int c0 = warpN + nf * 8 + tig * 2;
                float v0 = acc[mt][nf][hf * 2 + 0] + __ldg(bp + c0);
                float v1 = acc[mt][nf][hf * 2 + 1] + __ldg(bp + c0 + 1);
                if (MODE == 0) {
                    __half* C = (__half*)Cv;
                    *(__half2*)(C + (size_t)grow * Cstride + outCol + c0) =
                        __floats2half2_rn(v0, v1);
                } else if (MODE == 1) {
                    __half* C = (__half*)Cv;
                    *(__half2*)(C + (size_t)(myOff + grow) * Cstride + outCol + c0) =
                        __floats2half2_rn(gelu_f(v0), gelu_f(v1));
                } else {
                    float* C = (float*)Cv;
                    int crow = g_perm[myOff + grow];
                    *(float2*)(C + (size_t)crow * Cstride + outCol + c0) =
                        make_float2(v0, v1);
                }
            }
        }
    }
}

// ---------------- fused flash attention -------------------------------------
#define ATTN_SMEM (16384 + 32768 + 32768 + 1024)

__global__ __launch_bounds__(256)
void attn_kernel(float* __restrict__ X) {
    extern __shared__ char sm[];
    uint32_t sQ = smem_u32(sm);
    uint32_t sK = sQ + 16384;
    uint32_t sV = sQ + 49152;
    float* msk = (float*)(sm + 81920);

    int bh = blockIdx.y;
    int b = bh / NHEAD, h = bh % NHEAD;
    int qBase = blockIdx.x * 128;
    const __half* Qg = g_QKVh + (size_t)(b * Sq + qBase) * QKVN + h * 64;
    const __half* Kg = g_QKVh + (size_t)(b * Sq) * QKVN + Hdim + h * 64;
    const __half* Vg = g_QKVh + (size_t)(b * Sq) * QKVN + 2 * Hdim + h * 64;

    int tid = threadIdx.x, lane = tid & 31, wid = tid >> 5;
    int gid = lane >> 2, tig = lane & 3;

    {
        int r = tid >> 1, ub = (tid & 1) * 4;
        const __half* src = Qg + (size_t)r * QKVN + ub * 8;
#pragma unroll
        for (int i = 0; i < 4; i++)
            CPASYNC16(sQ + SWA((uint32_t)(r * 128 + (ub + i) * 16)), src + i * 8);
    }
    {
        const __half* ks = Kg + (size_t)tid * QKVN;
        const __half* vs = Vg + (size_t)tid * QKVN;
#pragma unroll
        for (int i = 0; i < 8; i++) {
            uint32_t o = SWA((uint32_t)(tid * 128 + i * 16));
            CPASYNC16(sK + o, ks + i * 8);
            CPASYNC16(sV + o, vs + i * 8);
        }
    }
    msk[tid] = g_mask[b * Sq + tid];
    CPCOMMIT();
    CPWAIT0();
    __syncthreads();

    int rA = lane & 15, cA = (lane >> 4) * 8;
    unsigned qf[4][4];
#pragma unroll
    for (int ks = 0; ks < 4; ks++)
        ldsm4(qf[ks], sQ + SWA((uint32_t)((wid * 16 + rA) * 128 + (ks * 16 + cA) * 2)));

    float oacc[8][4] = {};
    float m0 = -1e30f, m8 = -1e30f, l0 = 0.f, l8 = 0.f;
    int keyl = (lane & 7) + ((lane >> 4) << 3);
    int dml = ((lane >> 3) & 1) * 8;

    for (int kb = 0; kb < 4; kb++) {
        int keyBase = kb * 64;
        float sacc[8][4] = {};
#pragma unroll
        for (int ks = 0; ks < 4; ks++) {
#pragma unroll
            for (int nf2 = 0; nf2 < 4; nf2++) {
                unsigned kf[4];
                ldsm4(kf, sK + SWA((uint32_t)((keyBase + nf2 * 16 + keyl) * 128 +
                                              (ks * 16 + dml) * 2)));
                mma_f16(sacc[nf2 * 2],     qf[ks], kf[0], kf[1]);
                mma_f16(sacc[nf2 * 2 + 1], qf[ks], kf[2], kf[3]);
            }
        }
        float bm0 = -1e30f, bm8 = -1e30f;
#pragma unroll
        for (int nf = 0; nf < 8; nf++) {
            int c0 = keyBase + nf * 8 + tig * 2;
            float mk0 = msk[c0], mk1 = msk[c0 + 1];
            sacc[nf][0] += mk0; sacc[nf][1] += mk1;
            sacc[nf][2] += mk0; sacc[nf][3] += mk1;
            bm0 = fmaxf(bm0, fmaxf(sacc[nf][0], sacc[nf][1]));
            bm8 = fmaxf(bm8, fmaxf(sacc[nf][2], sacc[nf][3]));
        }
#pragma unroll
        for (int o = 1; o < 4; o <<= 1) {
            bm0 = fmaxf(bm0, __shfl_xor_sync(0xffffffffu, bm0, o));
            bm8 = fmaxf(bm8, __shfl_xor_sync(0xffffffffu, bm8, o));
        }
        float nm0 = fmaxf(m0, bm0), nm8 = fmaxf(m8, bm8);
        float sc0 = __expf(m0 - nm0), sc8 = __expf(m8 - nm8);
        m0 = nm0; m8 = nm8;
        float ls0 = 0.f, ls8 = 0.f;
        unsigned pa[4][4];
#pragma unroll
        for (int nf = 0; nf < 8; nf++) {
            float p0 = __expf(sacc[nf][0] - m0), p1 = __expf(sacc[nf][1] - m0);
            float p2 = __expf(sacc[nf][2] - m8), p3 = __expf(sacc[nf][3] - m8);
            ls0 += p0 + p1; ls8 += p2 + p3;
            unsigned h01 = h2u(__floats2half2_rn(p0, p1));
            unsigned h23 = h2u(__floats2half2_rn(p2, p3));
            int j = nf >> 1;
            if ((nf & 1) == 0) { pa[j][0] = h01; pa[j][1] = h23; }
            else               { pa[j][2] = h01; pa[j][3] = h23; }
        }
#pragma unroll
        for (int o = 1; o < 4; o <<= 1) {
            ls0 += __shfl_xor_sync(0xffffffffu, ls0, o);
            ls8 += __shfl_xor_sync(0xffffffffu, ls8, o);
        }
        l0 = l0 * sc0 + ls0;
        l8 = l8 * sc8 + ls8;
#pragma unroll
        for (int nd = 0; nd < 8; nd++) {
            oacc[nd][0] *= sc0; oacc[nd][1] *= sc0;
            oacc[nd][2] *= sc8; oacc[nd][3] *= sc8;
        }
#pragma unroll
        for (int j = 0; j < 4; j++) {
#pragma unroll
            for (int nd2 = 0; nd2 < 4; nd2++) {
                unsigned vf[4];
                ldsm4t(vf, sV + SWA((uint32_t)((keyBase + j * 16 + rA) * 128 +
                                               (nd2 * 16 + cA) * 2)));
                mma_f16(oacc[nd2 * 2],     pa[j], vf[0], vf[1]);
                mma_f16(oacc[nd2 * 2 + 1], pa[j], vf[2], vf[3]);
            }
        }
    }
    float inv0 = 1.f / l0, inv8 = 1.f / l8;
    int q0 = b * Sq + qBase + wid * 16 + gid;
#pragma unroll
    for (int nd = 0; nd < 8; nd++) {
        int col = h * 64 + nd * 8 + tig * 2;
        float* x0 = X + (size_t)q0 * Hdim + col;
        float* x8 = X + (size_t)(q0 + 8) * Hdim + col;
        float2 v0 = *(float2*)x0, v8 = *(float2*)x8;
        v0.x += oacc[nd][0] * inv0; v0.y += oacc[nd][1] * inv0;
        v8.x += oacc[nd][2] * inv8; v8.y += oacc[nd][3] * inv8;
        *(float2*)x0 = v0; *(float2*)x8 = v8;
    }
}

// ---------------- PE add ----------------------------------------------------
__global__ void pe_add_kernel(const float* __restrict__ xin, float* __restrict__ out) {
    int t = blockIdx.x;
    int s = t % Sq;
    const float* xr = xin + (size_t)t * Hdim;
    float* yr = out + (size_t)t * Hdim;
    for (int d = threadIdx.x; d < Hdim; d += blockDim.x) {
        int j = d >> 1;
        float div = expf(-(float)(2 * j) * (9.210340371976184f / (float)Hdim));
        float ang = (float)s * div;
        float pe = (d & 1) ? cosf(ang) : sinf(ang);
        yr[d] = xr[d] + pe;
    }
}

// ---------------- layernorm ---------------------------------------------------
__global__ void ln_kernel(const float* __restrict__ X, const float* __restrict__ w,
                          const float* __restrict__ b, __half* __restrict__ Y) {
    int row = blockIdx.x * 8 + (threadIdx.x >> 5);
    int lane = threadIdx.x & 31;
    const float4* xr = (const float4*)(X + (size_t)row * Hdim);
    float4 v[6];
    float s = 0.f;
#pragma unroll
    for (int i = 0; i < 6; i++) {
        v[i] = xr[lane + 32 * i];
        s += v[i].x + v[i].y + v[i].z + v[i].w;
    }
#pragma unroll
    for (int o = 16; o > 0; o >>= 1) s += __shfl_xor_sync(0xffffffffu, s, o);
    float mu = s * (1.0f / (float)Hdim);
    float q = 0.f;
#pragma unroll
    for (int i = 0; i < 6; i++) {
        float dx = v[i].x - mu, dy = v[i].y - mu, dz = v[i].z - mu, dw = v[i].w - mu;
        q += dx * dx + dy * dy + dz * dz + dw * dw;
    }
#pragma unroll
    for (int o = 16; o > 0; o >>= 1) q += __shfl_xor_sync(0xffffffffu, q, o);
    float rs = rsqrtf(q * (1.0f / (float)Hdim) + 1e-5f);
    const float4* wp = (const float4*)w;
    const float4* bpp = (const float4*)b;
    uint2* yr = (uint2*)(Y + (size_t)row * Hdim);
#pragma unroll
    for (int i = 0; i < 6; i++) {
        float4 wv = wp[lane + 32 * i], bv = bpp[lane + 32 * i];
        uint2 u;
        u.x = h2u(__floats2half2_rn((v[i].x - mu) * rs * wv.x + bv.x,
                                    (v[i].y - mu) * rs * wv.y + bv.y));
        u.y = h2u(__floats2half2_rn((v[i].z - mu) * rs * wv.z + bv.z,
                                    (v[i].w - mu) * rs * wv.w + bv.w));
        yr[lane + 32 * i] = u;
    }
}

// ---------------- scatter ----------------------------------------------------
__global__ void scatter_kernel(const float* __restrict__ X, float* __restrict__ Y) {
    int t = blockIdx.x;
    int v = g_idx[t];
    float4* yr = (float4*)(Y + (size_t)t * Hdim);
    int lane = threadIdx.x;
    if (v == 0) {
        if (lane < 192) yr[lane] = make_float4(0.f, 0.f, 0.f, 0.f);
    } else {
        const float4* xr = (const float4*)(X + (size_t)(v - 1) * Hdim);
        const float4* fr = (const float4*)(g_Fo + (size_t)(v - 1) * Hdim);
        if (lane < 192) {
            float4 a = xr[lane], f = fr[lane];
            yr[lane] = make_float4(a.x + f.x, a.y + f.y, a.z + f.z, a.w + f.w);
        }
    }
}

// ---------------- launch ----------------------------------------------------
#define SMEM_128 (3 * 16384 + 3 * 32768 / 2)   // 49152 + 49152 = 98304
#define SMEM_64  (3 * 16384 + 3 * 8192)        // 49152 + 24576 = 73728

extern "C" void kernel_launch(void* const* d_in, const int* in_sizes, int n_in,
                              void* d_out, int out_size) {
    const float* x    = (const float*)d_in[0];
    const void*  np   = d_in[1];
    const int*   ntp  = (const int*)d_in[2];
    const float* Wq   = (const float*)d_in[3];
    const float* bq   = (const float*)d_in[4];
    const float* Wk   = (const float*)d_in[5];
    const float* bk   = (const float*)d_in[6];
    const float* Wv   = (const float*)d_in[7];
    const float* bv   = (const float*)d_in[8];
    const float* ln1w = (const float*)d_in[9];
    const float* ln1b = (const float*)d_in[10];
    const float* ln2w = (const float*)d_in[11];
    const float* ln2b = (const float*)d_in[12];
    const float* W1   = (const float*)d_in[13];
    const float* b1   = (const float*)d_in[14];
    const float* W2   = (const float*)d_in[15];
    const float* b2   = (const float*)d_in[16];
    float* out = (float*)d_out;

    float *Xa, *Xb, *Fo, *bpk;
    __half *Hh, *QKVh, *Midh, *Wqkvh, *W1h, *W2h;
    cudaGetSymbolAddress((void**)&Xa, g_Xa);
    cudaGetSymbolAddress((void**)&Xb, g_Xb);
    cudaGetSymbolAddress((void**)&Hh, g_Hh);
    cudaGetSymbolAddress((void**)&QKVh, g_QKVh);
    cudaGetSymbolAddress((void**)&Midh, g_midh);
    cudaGetSymbolAddress((void**)&Fo, g_Fo);
    cudaGetSymbolAddress((void**)&Wqkvh, g_Wqkvh);
    cudaGetSymbolAddress((void**)&W1h, g_W1h);
    cudaGetSymbolAddress((void**)&W2h, g_W2h);
    cudaGetSymbolAddress((void**)&bpk, g_bpk);

    cudaFuncSetAttribute(hgemm<0, 128>, cudaFuncAttributeMaxDynamicSharedMemorySize, SMEM_128);
    cudaFuncSetAttribute(hgemm<1, 128>, cudaFuncAttributeMaxDynamicSharedMemorySize, SMEM_128);
    cudaFuncSetAttribute(hgemm<2, 64>,  cudaFuncAttributeMaxDynamicSharedMemorySize, SMEM_64);
    cudaFuncSetAttribute(attn_kernel,   cudaFuncAttributeMaxDynamicSharedMemorySize, ATTN_SMEM);

    pack_qkv_h<<<dim3((HH / 8 + 255) / 256, 6), 256>>>(
        (const float4*)Wq, (const float4*)Wk, (const float4*)Wv);
    f2h_kernel<<<4096, 256>>>((const float4*)W1, (uint4*)W1h, 2 * NEXP * Hdim * FFd / 8);
    f2h_kernel<<<4096, 256>>>((const float4*)W2, (uint4*)W2h, 2 * NEXP * FFd * Hdim / 8);
    pack_bias_kernel<<<(2 * QKVN + 255) / 256, 256>>>(bq, bk, bv);

    setup_kernel<<<1, 256>>>(np, ntp);
    pe_add_kernel<<<TT, 256>>>(x, Xa);

    float* Xcur = Xa;
    for (int l = 0; l < 2; l++) {
        float* Xnext = (l == 0) ? Xb : out;
        size_t lH = (size_t)l * Hdim;
        // --- attention ---
        ln_kernel<<<TT / 8, 256>>>(Xcur, ln1w + lH, ln1b + lH, Hh);
        hgemm<0, 128><<<dim3(16, 18), 256, SMEM_128>>>(
            Hh, Wqkvh + (size_t)l * 3 * HH, bpk + l * QKVN, QKVh, Hdim, Hdim, QKVN);
        attn_kernel<<<dim3(2, NBH), 256, ATTN_SMEM>>>(Xcur);
        // --- expert FFN ---
        ln_kernel<<<TT / 8, 256>>>(Xcur, ln2w + lH, ln2b + lH, Hh);
        hgemm<1, 128><<<dim3(16, FFd / 128, NEXP), 256, SMEM_128>>>(
            Hh, W1h + (size_t)l * NEXP * Hdim * FFd, b1 + (size_t)l * NEXP * FFd,
            Midh, Hdim, FFd, FFd);
        hgemm<2, 64><<<dim3(16, Hdim / 64, NEXP), 256, SMEM_64>>>(
            Midh, W2h + (size_t)l * NEXP * FFd * Hdim, b2 + (size_t)l * NEXP * Hdim,
            Fo, FFd, Hdim, Hdim);
        scatter_kernel<<<TT, 256>>>(Xcur, Xnext);
        Xcur = Xnext;
    }
}

// round 16
// speedup vs baseline: 1.0407x; 1.0407x over previous
#include <cuda_runtime.h>
#include <cuda_fp16.h>
#include <math.h>
#include <stdint.h>

#define TT    2048
#define Hdim  768
#define Sq    256
#define NBATCH 8
#define NHEAD 12
#define FFd   3072
#define NEXP  4
#define QKVN  2304
#define NBH   (NBATCH * NHEAD)
#define HH    (Hdim * Hdim)

// ---------------- scratch (device globals) ---------------------------------
__device__ float  g_Xa[TT * Hdim];
__device__ float  g_Xb[TT * Hdim];
__device__ __half g_Hh[TT * Hdim];
__device__ __half g_QKVh[TT * QKVN];
__device__ __half g_midh[TT * FFd];
__device__ float  g_mask[TT];
__device__ int    g_idx[TT];
__device__ int    g_perm[TT];
__device__ int    g_inv[TT];
__device__ int    g_cnt[NEXP];
__device__ int    g_off[NEXP];
__device__ __half g_Wqkvh[2 * 3 * HH];
__device__ __half g_W1h[2 * NEXP * Hdim * FFd];
__device__ __half g_W2h[2 * NEXP * FFd * Hdim];
__device__ float  g_bpk[2 * QKVN];

// ---------------- helpers ---------------------------------------------------
__device__ __forceinline__ float gelu_f(float v) {
    return 0.5f * v * (1.0f + erff(v * 0.70710678118654752f));
}
__device__ __forceinline__ uint32_t smem_u32(const void* p) {
    uint32_t a;
    asm("{ .reg .u64 t; cvta.to.shared.u64 t, %1; cvt.u32.u64 %0, t; }" : "=r"(a) : "l"(p));
    return a;
}
#define SWA(o) ((o) ^ (((o) >> 3) & 0x70))   // 128B rows
#define SWB(o) ((o) ^ (((o) >> 4) & 0x70))   // 256B rows

__device__ __forceinline__ void ldsm4(unsigned r[4], uint32_t addr) {
    asm volatile("ldmatrix.sync.aligned.m8n8.x4.shared.b16 {%0,%1,%2,%3}, [%4];"
                 : "=r"(r[0]), "=r"(r[1]), "=r"(r[2]), "=r"(r[3]) : "r"(addr));
}
__device__ __forceinline__ void ldsm4t(unsigned r[4], uint32_t addr) {
    asm volatile("ldmatrix.sync.aligned.m8n8.x4.trans.shared.b16 {%0,%1,%2,%3}, [%4];"
                 : "=r"(r[0]), "=r"(r[1]), "=r"(r[2]), "=r"(r[3]) : "r"(addr));
}
__device__ __forceinline__ void mma_f16(float c[4], const unsigned a[4],
                                        unsigned b0, unsigned b1) {
    asm volatile(
        "mma.sync.aligned.m16n8k16.row.col.f32.f16.f16.f32 "
        "{%0,%1,%2,%3}, {%4,%5,%6,%7}, {%8,%9}, {%0,%1,%2,%3};\n"
        : "+f"(c[0]), "+f"(c[1]), "+f"(c[2]), "+f"(c[3])
        : "r"(a[0]), "r"(a[1]), "r"(a[2]), "r"(a[3]), "r"(b0), "r"(b1));
}
#define CPASYNC16(dst, src) \
    asm volatile("cp.async.cg.shared.global [%0], [%1], 16;" :: "r"(dst), "l"(src))
#define CPCOMMIT() asm volatile("cp.async.commit_group;" ::: "memory")
#define CPWAIT1() asm volatile("cp.async.wait_group 1;" ::: "memory")
#define CPWAIT0() asm volatile("cp.async.wait_group 0;" ::: "memory")

__device__ __forceinline__ unsigned h2u(__half2 h) { return *(unsigned*)&h; }

// ---------------- weight conversion ------------------------------------------
__global__ void f2h_kernel(const float4* __restrict__ src, uint4* __restrict__ dst, int n8) {
    for (int i = blockIdx.x * blockDim.x + threadIdx.x; i < n8;
         i += gridDim.x * blockDim.x) {
        float4 v0 = src[i * 2], v1 = src[i * 2 + 1];
        uint4 u;
        u.x = h2u(__floats2half2_rn(v0.x, v0.y));
        u.y = h2u(__floats2half2_rn(v0.z, v0.w));
        u.z = h2u(__floats2half2_rn(v1.x, v1.y));
        u.w = h2u(__floats2half2_rn(v1.z, v1.w));
        dst[i] = u;
    }
}
__global__ void pack_qkv_h(const float4* __restrict__ Wq, const float4* __restrict__ Wk,
                           const float4* __restrict__ Wv) {
    int y = blockIdx.y, l = y / 3, w = y % 3;
    const float4* src = ((w == 0) ? Wq : (w == 1) ? Wk : Wv) + (size_t)l * (HH / 4);
    uint4* dst = (uint4*)(g_Wqkvh + (size_t)y * HH);
    int i = blockIdx.x * 256 + threadIdx.x;
    if (i < HH / 8) {
        float4 v0 = src[i * 2], v1 = src[i * 2 + 1];
        uint4 u;
        u.x = h2u(__floats2half2_rn(v0.x, v0.y));
        u.y = h2u(__floats2half2_rn(v0.z, v0.w));
        u.z = h2u(__floats2half2_rn(v1.x, v1.y));
        u.w = h2u(__floats2half2_rn(v1.z, v1.w));
        dst[i] = u;
    }
}
__global__ void pack_bias_kernel(const float* __restrict__ bq, const float* __restrict__ bk,
                                 const float* __restrict__ bv) {
    int i = blockIdx.x * 256 + threadIdx.x;
    if (i < 2 * QKVN) {
        int l = i / QKVN, c = i % QKVN;
        int w = c / Hdim, o = c % Hdim;
        const float* s = (w == 0) ? bq : (w == 1) ? bk : bv;
        g_bpk[i] = s[l * Hdim + o];
    }
}

// ---------------- setup: dtype detect + mask + routing + inverse perm --------
__global__ void setup_kernel(const void* __restrict__ note_pos_raw,
                             const int* __restrict__ ntp) {
    __shared__ int s_or[256];
    __shared__ int s_is64;
    __shared__ int sc[NEXP], so[NEXP], scur[NEXP];
    const int* w = (const int*)note_pos_raw;
    int tid = threadIdx.x;
    int acc = 0;
    for (int i = tid; i < TT / 2; i += 256) acc |= w[2 * i + 1];
    s_or[tid] = acc; __syncthreads();
    for (int st = 128; st > 0; st >>= 1) {
        if (tid < st) s_or[tid] |= s_or[tid + st];
        __syncthreads();
    }
    if (tid == 0) s_is64 = (s_or[0] == 0);
    if (tid < NEXP) { sc[tid] = 0; scur[tid] = 0; }
    __syncthreads();
    bool is64 = (s_is64 != 0);
    for (int t = tid; t < TT; t += 256) {
        long long v = is64 ? ((const long long*)note_pos_raw)[t] : (long long)w[t];
        g_idx[t] = (int)v;
        g_inv[t] = -1;
        g_mask[t] = (v != 0) ? 0.0f : -10000.0f;
        atomicAdd(&sc[ntp[t]], 1);
    }
    __syncthreads();
    if (tid == 0) {
        int o = 0;
        for (int e = 0; e < NEXP; e++) { so[e] = o; o += sc[e]; }
    }
    __syncthreads();
    for (int t = tid; t < TT; t += 256) {
        int e = ntp[t];
        int p = so[e] + atomicAdd(&scur[e], 1);
        g_perm[p] = t;
    }
    __syncthreads();
    // inverse scatter map: g_inv[v-1] = t  (needs g_idx complete -> after sync)
    for (int t = tid; t < TT; t += 256) {
        int v = g_idx[t];
        if (v != 0) g_inv[v - 1] = t;
    }
    if (tid < NEXP) { g_cnt[tid] = sc[tid]; g_off[tid] = so[tid]; }
}

// ---------------- zero invalid output rows (runs every replay) ---------------
__global__ void zero_invalid_kernel(float* __restrict__ Y0, float* __restrict__ Y1) {
    int t = blockIdx.x;
    if (g_idx[t] != 0) return;
    float* y = (blockIdx.y == 0) ? Y0 : Y1;
    float4* yr = (float4*)(y + (size_t)t * Hdim);
    if (threadIdx.x < 192) yr[threadIdx.x] = make_float4(0.f, 0.f, 0.f, 0.f);
}

// ---------------- fp16 mma GEMM, 2-stage cp.async pipeline -------------------
// MODE 0: QKV fused, fp16 out. MODE 1: FFN1 gather+gelu, fp16 out sorted.
// MODE 2: FFN2 + residual + scatter: Y[inv[r]] = X[r] + acc, fp32.
extern __shared__ char dynsm[];

template <int MODE, int BNT>
__global__ __launch_bounds__(256)
void hgemm(const __half* __restrict__ A, const __half* __restrict__ W,
           const float* __restrict__ bias, void* __restrict__ Cv,
           const float* __restrict__ Xres, int K, int Nw, int Cstride) {
    constexpr int NF = BNT / 32;
    constexpr int NG = BNT / 64;
    constexpr int BB = 64 * BNT * 2;
    constexpr int UPT = BNT / 32;

    int rowBase = blockIdx.x * 128;
    int myCnt = TT, myOff = 0;
    const __half* Wp;
    const float* bp;
    int colW, outCol;
    if (MODE == 0) {
        int y = blockIdx.y, ws = y / 6, yc = y % 6;
        Wp = W + (size_t)ws * HH;
        colW = yc * 128;
        outCol = y * 128;
        bp = bias + outCol;
    } else {
        int e = blockIdx.z;
        myCnt = g_cnt[e]; myOff = g_off[e];
        if (rowBase >= myCnt) return;
        Wp = W + (size_t)e * K * Nw;
        colW = blockIdx.y * BNT;
        outCol = colW;
        bp = bias + (size_t)e * Nw + colW;
    }

    int tid = threadIdx.x;
    int lane = tid & 31, wid = tid >> 5;
    int warpM = (wid >> 2) * 64;
    int warpN = (wid & 3) * (BNT / 4);
    int gid = lane >> 2, tig = lane & 3;

    uint32_t smA = smem_u32(dynsm);

    int m = tid >> 1;
    int ukb = (tid & 1) * 4;
    bool aValid;
    const __half* ap;
    if (MODE == 0) {
        aValid = true;
        ap = A + (size_t)(rowBase + m) * K;
    } else if (MODE == 1) {
        aValid = (rowBase + m) < myCnt;
        ap = A + (size_t)(aValid ? g_perm[myOff + rowBase + m] : 0) * K;
    } else {
        aValid = (rowBase + m) < myCnt;
        ap = A + (size_t)(myOff + (aValid ? rowBase + m : 0)) * K;
    }
    uint32_t aOff[4];
#pragma unroll
    for (int i = 0; i < 4; i++) aOff[i] = SWA((uint32_t)(m * 128 + (ukb + i) * 16));

    int bk_ = tid >> 2;
    int unb = (tid & 3) * UPT;
    uint32_t bOff[UPT];
#pragma unroll
    for (int i = 0; i < UPT; i++) {
        uint32_t o = (uint32_t)(bk_ * (BNT * 2) + (unb + i) * 16);
        bOff[i] = (BNT == 128) ? SWB(o) : SWA(o);
    }

    int nCh = K >> 6;
    float acc[4][NF][4] = {};

    {
        uint32_t ab = smA, bb = smA + 32768;
        const __half* as = ap + ukb * 8;
        const __half* bs = Wp + (size_t)bk_ * Nw + colW + unb * 8;
#pragma unroll
        for (int i = 0; i < 4; i++) CPASYNC16(ab + aOff[i], as + i * 8);
#pragma unroll
        for (int i = 0; i < UPT; i++) CPASYNC16(bb + bOff[i], bs + i * 8);
        CPCOMMIT();
    }

    int rA = lane & 15;
    int cA = (lane >> 4) * 8;

    for (int c = 0; c < nCh; c++) {
        if (c + 1 < nCh) {
            int nb = (c + 1) & 1;
            uint32_t ab = smA + nb * 16384, bb = smA + 32768 + nb * BB;
            const __half* as = ap + (c + 1) * 64 + ukb * 8;
            const __half* bs = Wp + (size_t)((c + 1) * 64 + bk_) * Nw + colW + unb * 8;
#pragma unroll
            for (int i = 0; i < 4; i++) CPASYNC16(ab + aOff[i], as + i * 8);
#pragma unroll
            for (int i = 0; i < UPT; i++) CPASYNC16(bb + bOff[i], bs + i * 8);
            CPCOMMIT();
            CPWAIT1();
        } else {
            CPWAIT0();
        }
        __syncthreads();

        uint32_t aB = smA + (c & 1) * 16384;
        uint32_t bB = smA + 32768 + (c & 1) * BB;
#pragma unroll
        for (int ks = 0; ks < 4; ks++) {
            unsigned afr[4][4], bfr[NG][4];
#pragma unroll
            for (int mt = 0; mt < 4; mt++)
                ldsm4(afr[mt], aB + SWA((uint32_t)((warpM + mt * 16 + rA) * 128 +
                                                   (ks * 16 + cA) * 2)));
#pragma unroll
            for (int ng = 0; ng < NG; ng++) {
                uint32_t o = (uint32_t)((ks * 16 + rA) * (BNT * 2) +
                                        (warpN + ng * 16 + cA) * 2);
                ldsm4t(bfr[ng], bB + ((BNT == 128) ? SWB(o) : SWA(o)));
            }
#pragma unroll
            for (int mt = 0; mt < 4; mt++)
#pragma unroll
                for (int nf = 0; nf < NF; nf++)
                    mma_f16(acc[mt][nf], afr[mt],
                            bfr[nf >> 1][(nf & 1) * 2], bfr[nf >> 1][(nf & 1) * 2 + 1]);
        }
        __syncthreads();
    }

#pragma unroll
    for (int mt = 0; mt < 4; mt++) {
#pragma unroll
        for (int hf = 0; hf < 2; hf++) {
            int grow = rowBase + warpM + mt * 16 + gid + hf * 8;
            if (MODE != 0 && grow >= myCnt) continue;
            int rtok = 0, tdst = 0;
            if (MODE == 2) {
                rtok = g_perm[myOff + grow];
                tdst = g_inv[rtok];
                if (tdst < 0) continue;
            }
#pragma unroll
            for (int nf = 0; nf < NF; nf++) {
                int c0 = warpN + nf * 8 + tig * 2;
                float v0 = acc[mt][nf][hf * 2 + 0] + __ldg(bp + c0);
                float v1 = acc[mt][nf][hf * 2 + 1] + __ldg(bp + c0 + 1);
                if (MODE == 0) {
                    __half* C = (__half*)Cv;
                    *(__half2*)(C + (size_t)grow * Cstride + outCol + c0) =
                        __floats2half2_rn(v0, v1);
                } else if (MODE == 1) {
                    __half* C = (__half*)Cv;
                    *(__half2*)(C + (size_t)(myOff + grow) * Cstride + outCol + c0) =
                        __floats2half2_rn(gelu_f(v0), gelu_f(v1));
                } else {
                    float* C = (float*)Cv;
                    float2 xr = *(const float2*)(Xres + (size_t)rtok * Cstride + outCol + c0);
                    *(float2*)(C + (size_t)tdst * Cstride + outCol + c0) =
                        make_float2(xr.x + v0, xr.y + v1);
                }
            }
        }
    }
}

// ---------------- fused flash attention -------------------------------------
#define ATTN_SMEM (16384 + 32768 + 32768 + 1024)

__global__ __launch_bounds__(256)
void attn_kernel(float* __restrict__ X) {
    extern __shared__ char sm[];
    uint32_t sQ = smem_u32(sm);
    uint32_t sK = sQ + 16384;
    uint32_t sV = sQ + 49152;
    float* msk = (float*)(sm + 81920);

    int bh = blockIdx.y;
    int b = bh / NHEAD, h = bh % NHEAD;
    int qBase = blockIdx.x * 128;
    const __half* Qg = g_QKVh + (size_t)(b * Sq + qBase) * QKVN + h * 64;
    const __half* Kg = g_QKVh + (size_t)(b * Sq) * QKVN + Hdim + h * 64;
    const __half* Vg = g_QKVh + (size_t)(b * Sq) * QKVN + 2 * Hdim + h * 64;

    int tid = threadIdx.x, lane = tid & 31, wid = tid >> 5;
    int gid = lane >> 2, tig = lane & 3;

    {
        int r = tid >> 1, ub = (tid & 1) * 4;
        const __half* src = Qg + (size_t)r * QKVN + ub * 8;
#pragma unroll
        for (int i = 0; i < 4; i++)
            CPASYNC16(sQ + SWA((uint32_t)(r * 128 + (ub + i) * 16)), src + i * 8);
    }
    {
        const __half* ks = Kg + (size_t)tid * QKVN;
        const __half* vs = Vg + (size_t)tid * QKVN;
#pragma unroll
        for (int i = 0; i < 8; i++) {
            uint32_t o = SWA((uint32_t)(tid * 128 + i * 16));
            CPASYNC16(sK + o, ks + i * 8);
            CPASYNC16(sV + o, vs + i * 8);
        }
    }
    msk[tid] = g_mask[b * Sq + tid];
    CPCOMMIT();
    CPWAIT0();
    __syncthreads();

    int rA = lane & 15, cA = (lane >> 4) * 8;
    unsigned qf[4][4];
#pragma unroll
    for (int ks = 0; ks < 4; ks++)
        ldsm4(qf[ks], sQ + SWA((uint32_t)((wid * 16 + rA) * 128 + (ks * 16 + cA) * 2)));

    float oacc[8][4] = {};
    float m0 = -1e30f, m8 = -1e30f, l0 = 0.f, l8 = 0.f;
    int keyl = (lane & 7) + ((lane >> 4) << 3);
    int dml = ((lane >> 3) & 1) * 8;

    for (int kb = 0; kb < 4; kb++) {
        int keyBase = kb * 64;
        float sacc[8][4] = {};
#pragma unroll
        for (int ks = 0; ks < 4; ks++) {
#pragma unroll
            for (int nf2 = 0; nf2 < 4; nf2++) {
                unsigned kf[4];
                ldsm4(kf, sK + SWA((uint32_t)((keyBase + nf2 * 16 + keyl) * 128 +
                                              (ks * 16 + dml) * 2)));
                mma_f16(sacc[nf2 * 2],     qf[ks], kf[0], kf[1]);
                mma_f16(sacc[nf2 * 2 + 1], qf[ks], kf[2], kf[3]);
            }
        }
        float bm0 = -1e30f, bm8 = -1e30f;
#pragma unroll
        for (int nf = 0; nf < 8; nf++) {
            int c0 = keyBase + nf * 8 + tig * 2;
            float mk0 = msk[c0], mk1 = msk[c0 + 1];
            sacc[nf][0] += mk0; sacc[nf][1] += mk1;
            sacc[nf][2] += mk0; sacc[nf][3] += mk1;
            bm0 = fmaxf(bm0, fmaxf(sacc[nf][0], sacc[nf][1]));
            bm8 = fmaxf(bm8, fmaxf(sacc[nf][2], sacc[nf][3]));
        }
#pragma unroll
        for (int o = 1; o < 4; o <<= 1) {
            bm0 = fmaxf(bm0, __shfl_xor_sync(0xffffffffu, bm0, o));
            bm8 = fmaxf(bm8, __shfl_xor_sync(0xffffffffu, bm8, o));
        }
        float nm0 = fmaxf(m0, bm0), nm8 = fmaxf(m8, bm8);
        float sc0 = __expf(m0 - nm0), sc8 = __expf(m8 - nm8);
        m0 = nm0; m8 = nm8;
        float ls0 = 0.f, ls8 = 0.f;
        unsigned pa[4][4];
#pragma unroll
        for (int nf = 0; nf < 8; nf++) {
            float p0 = __expf(sacc[nf][0] - m0), p1 = __expf(sacc[nf][1] - m0);
            float p2 = __expf(sacc[nf][2] - m8), p3 = __expf(sacc[nf][3] - m8);
            ls0 += p0 + p1; ls8 += p2 + p3;
            unsigned h01 = h2u(__floats2half2_rn(p0, p1));
            unsigned h23 = h2u(__floats2half2_rn(p2, p3));
            int j = nf >> 1;
            if ((nf & 1) == 0) { pa[j][0] = h01; pa[j][1] = h23; }
            else               { pa[j][2] = h01; pa[j][3] = h23; }
        }
#pragma unroll
        for (int o = 1; o < 4; o <<= 1) {
            ls0 += __shfl_xor_sync(0xffffffffu, ls0, o);
            ls8 += __shfl_xor_sync(0xffffffffu, ls8, o);
        }
        l0 = l0 * sc0 + ls0;
        l8 = l8 * sc8 + ls8;
#pragma unroll
        for (int nd = 0; nd < 8; nd++) {
            oacc[nd][0] *= sc0; oacc[nd][1] *= sc0;
            oacc[nd][2] *= sc8; oacc[nd][3] *= sc8;
        }
#pragma unroll
        for (int j = 0; j < 4; j++) {
#pragma unroll
            for (int nd2 = 0; nd2 < 4; nd2++) {
                unsigned vf[4];
                ldsm4t(vf, sV + SWA((uint32_t)((keyBase + j * 16 + rA) * 128 +
                                               (nd2 * 16 + cA) * 2)));
                mma_f16(oacc[nd2 * 2],     pa[j], vf[0], vf[1]);
                mma_f16(oacc[nd2 * 2 + 1], pa[j], vf[2], vf[3]);
            }
        }
    }
    float inv0 = 1.f / l0, inv8 = 1.f / l8;
    int q0 = b * Sq + qBase + wid * 16 + gid;
#pragma unroll
    for (int nd = 0; nd < 8; nd++) {
        int col = h * 64 + nd * 8 + tig * 2;
        float* x0 = X + (size_t)q0 * Hdim + col;
        float* x8 = X + (size_t)(q0 + 8) * Hdim + col;
        float2 v0 = *(float2*)x0, v8 = *(float2*)x8;
        v0.x += oacc[nd][0] * inv0; v0.y += oacc[nd][1] * inv0;
        v8.x += oacc[nd][2] * inv8; v8.y += oacc[nd][3] * inv8;
        *(float2*)x0 = v0; *(float2*)x8 = v8;
    }
}

// ---------------- PE add ----------------------------------------------------
__global__ void pe_add_kernel(const float* __restrict__ xin, float* __restrict__ out) {
    int t = blockIdx.x;
    int s = t % Sq;
    const float* xr = xin + (size_t)t * Hdim;
    float* yr = out + (size_t)t * Hdim;
    for (int d = threadIdx.x; d < Hdim; d += blockDim.x) {
        int j = d >> 1;
        float div = expf(-(float)(2 * j) * (9.210340371976184f / (float)Hdim));
        float ang = (float)s * div;
        float pe = (d & 1) ? cosf(ang) : sinf(ang);
        yr[d] = xr[d] + pe;
    }
}

// ---------------- layernorm ---------------------------------------------------
__global__ void ln_kernel(const float* __restrict__ X, const float* __restrict__ w,
                          const float* __restrict__ b, __half* __restrict__ Y) {
    int row = blockIdx.x * 8 + (threadIdx.x >> 5);
    int lane = threadIdx.x & 31;
    const float4* xr = (const float4*)(X + (size_t)row * Hdim);
    float4 v[6];
    float s = 0.f;
#pragma unroll
    for (int i = 0; i < 6; i++) {
        v[i] = xr[lane + 32 * i];
        s += v[i].x + v[i].y + v[i].z + v[i].w;
    }
#pragma unroll
    for (int o = 16; o > 0; o >>= 1) s += __shfl_xor_sync(0xffffffffu, s, o);
    float mu = s * (1.0f / (float)Hdim);
    float q = 0.f;
#pragma unroll
    for (int i = 0; i < 6; i++) {
        float dx = v[i].x - mu, dy = v[i].y - mu, dz = v[i].z - mu, dw = v[i].w - mu;
        q += dx * dx + dy * dy + dz * dz + dw * dw;
    }
#pragma unroll
    for (int o = 16; o > 0; o >>= 1) q += __shfl_xor_sync(0xffffffffu, q, o);
    float rs = rsqrtf(q * (1.0f / (float)Hdim) + 1e-5f);
    const float4* wp = (const float4*)w;
    const float4* bpp = (const float4*)b;
    uint2* yr = (uint2*)(Y + (size_t)row * Hdim);
#pragma unroll
    for (int i = 0; i < 6; i++) {
        float4 wv = wp[lane + 32 * i], bv = bpp[lane + 32 * i];
        uint2 u;
        u.x = h2u(__floats2half2_rn((v[i].x - mu) * rs * wv.x + bv.x,
                                    (v[i].y - mu) * rs * wv.y + bv.y));
        u.y = h2u(__floats2half2_rn((v[i].z - mu) * rs * wv.z + bv.z,
                                    (v[i].w - mu) * rs * wv.w + bv.w));
        yr[lane + 32 * i] = u;
    }
}

// ---------------- launch ----------------------------------------------------
#define SMEM_128 65536
#define SMEM_64  49152

extern "C" void kernel_launch(void* const* d_in, const int* in_sizes, int n_in,
                              void* d_out, int out_size) {
    const float* x    = (const float*)d_in[0];
    const void*  np   = d_in[1];
    const int*   ntp  = (const int*)d_in[2];
    const float* Wq   = (const float*)d_in[3];
    const float* bq   = (const float*)d_in[4];
    const float* Wk   = (const float*)d_in[5];
    const float* bk   = (const float*)d_in[6];
    const float* Wv   = (const float*)d_in[7];
    const float* bv   = (const float*)d_in[8];
    const float* ln1w = (const float*)d_in[9];
    const float* ln1b = (const float*)d_in[10];
    const float* ln2w = (const float*)d_in[11];
    const float* ln2b = (const float*)d_in[12];
    const float* W1   = (const float*)d_in[13];
    const float* b1   = (const float*)d_in[14];
    const float* W2   = (const float*)d_in[15];
    const float* b2   = (const float*)d_in[16];
    float* out = (float*)d_out;

    float *Xa, *Xb, *bpk;
    __half *Hh, *QKVh, *Midh, *Wqkvh, *W1h, *W2h;
    cudaGetSymbolAddress((void**)&Xa, g_Xa);
    cudaGetSymbolAddress((void**)&Xb, g_Xb);
    cudaGetSymbolAddress((void**)&Hh, g_Hh);
    cudaGetSymbolAddress((void**)&QKVh, g_QKVh);
    cudaGetSymbolAddress((void**)&Midh, g_midh);
    cudaGetSymbolAddress((void**)&Wqkvh, g_Wqkvh);
    cudaGetSymbolAddress((void**)&W1h, g_W1h);
    cudaGetSymbolAddress((void**)&W2h, g_W2h);
    cudaGetSymbolAddress((void**)&bpk, g_bpk);

    cudaFuncSetAttribute(hgemm<0, 128>, cudaFuncAttributeMaxDynamicSharedMemorySize, SMEM_128);
    cudaFuncSetAttribute(hgemm<1, 128>, cudaFuncAttributeMaxDynamicSharedMemorySize, SMEM_128);
    cudaFuncSetAttribute(hgemm<2, 64>,  cudaFuncAttributeMaxDynamicSharedMemorySize, SMEM_64);
    cudaFuncSetAttribute(attn_kernel,   cudaFuncAttributeMaxDynamicSharedMemorySize, ATTN_SMEM);

    // one-time side stream + events (created outside any capture; reused)
    static cudaStream_t s1 = nullptr;
    static cudaEvent_t eFork = nullptr, eQ = nullptr, eW = nullptr;
    if (s1 == nullptr) {
        cudaStreamCreateWithFlags(&s1, cudaStreamNonBlocking);
        cudaEventCreateWithFlags(&eFork, cudaEventDisableTiming);
        cudaEventCreateWithFlags(&eQ, cudaEventDisableTiming);
        cudaEventCreateWithFlags(&eW, cudaEventDisableTiming);
    }

    // ---- fork: weight conversions on side stream, overlapped with prologue
    cudaEventRecord(eFork, 0);
    cudaStreamWaitEvent(s1, eFork, 0);
    pack_qkv_h<<<dim3((HH / 8 + 255) / 256, 6), 256, 0, s1>>>(
        (const float4*)Wq, (const float4*)Wk, (const float4*)Wv);
    pack_bias_kernel<<<(2 * QKVN + 255) / 256, 256, 0, s1>>>(bq, bk, bv);
    cudaEventRecord(eQ, s1);
    f2h_kernel<<<4096, 256, 0, s1>>>((const float4*)W1, (uint4*)W1h,
                                     2 * NEXP * Hdim * FFd / 8);
    f2h_kernel<<<4096, 256, 0, s1>>>((const float4*)W2, (uint4*)W2h,
                                     2 * NEXP * FFd * Hdim / 8);
    cudaEventRecord(eW, s1);

    // ---- main stream prologue
    setup_kernel<<<1, 256>>>(np, ntp);
    zero_invalid_kernel<<<dim3(TT, 2), 192>>>(Xb, out);
    pe_add_kernel<<<TT, 256>>>(x, Xa);

    bool joinedW = false;
    float* Xcur = Xa;
    for (int l = 0; l < 2; l++) {
        float* Xnext = (l == 0) ? Xb : out;
        size_t lH = (size_t)l * Hdim;
        // --- attention ---
        ln_kernel<<<TT / 8, 256>>>(Xcur, ln1w + lH, ln1b + lH, Hh);
        if (l == 0) cudaStreamWaitEvent(0, eQ, 0);
        hgemm<0, 128><<<dim3(16, 18), 256, SMEM_128>>>(
            Hh, Wqkvh + (size_t)l * 3 * HH, bpk + l * QKVN, QKVh, nullptr,
            Hdim, Hdim, QKVN);
        attn_kernel<<<dim3(2, NBH), 256, ATTN_SMEM>>>(Xcur);
        // --- expert FFN ---
        ln_kernel<<<TT / 8, 256>>>(Xcur, ln2w + lH, ln2b + lH, Hh);
        if (!joinedW) { cudaStreamWaitEvent(0, eW, 0); joinedW = true; }
        hgemm<1, 128><<<dim3(16, FFd / 128, NEXP), 256, SMEM_128>>>(
            Hh, W1h + (size_t)l * NEXP * Hdim * FFd, b1 + (size_t)l * NEXP * FFd,
            Midh, nullptr, Hdim, FFd, FFd);
        hgemm<2, 64><<<dim3(16, Hdim / 64, NEXP), 256, SMEM_64>>>(
            Midh, W2h + (size_t)l * NEXP * FFd * Hdim, b2 + (size_t)l * NEXP * Hdim,
            Xnext, Xcur, FFd, Hdim, Hdim);
        Xcur = Xnext;
    }
}